// round 1
// baseline (speedup 1.0000x reference)
#include <cuda_runtime.h>
#include <cstdint>

// Problem constants
#define B_  8
#define C_  128
#define H_  256
#define W_  256
#define KB_ 4
#define OC_ 128

// Scratch (static device arrays; no allocation)
__device__ float g_pooled[B_ * C_];          // [B, C] GAP results
__device__ float g_dynk[B_ * C_ * 9];        // [B, C, 3, 3] dynamic depthwise kernels
__device__ float g_pwT[C_ * OC_];            // pw_w transposed: [C, OC]

// ---------------------------------------------------------------------------
// Kernel 1: global average pool. One block per (b,c) plane of 65536 floats.
// ---------------------------------------------------------------------------
__global__ void pool_kernel(const float* __restrict__ x) {
    const int plane = blockIdx.x;            // b*C + c
    const int t = threadIdx.x;               // 256 threads
    const float4* p = reinterpret_cast<const float4*>(x + (size_t)plane * (H_ * W_));
    float s = 0.f;
#pragma unroll 8
    for (int it = 0; it < 64; it++) {
        float4 v = p[it * 256 + t];
        s += (v.x + v.y) + (v.z + v.w);
    }
    __shared__ float red[256];
    red[t] = s;
    __syncthreads();
    for (int st = 128; st > 0; st >>= 1) {
        if (t < st) red[t] += red[t + st];
        __syncthreads();
    }
    if (t == 0) g_pooled[plane] = red[0] * (1.f / (H_ * W_));
}

// ---------------------------------------------------------------------------
// Kernel 2: attention logits -> softmax -> dynamic depthwise kernel per (b,c).
// One block per batch, 128 threads (one per channel).
// ---------------------------------------------------------------------------
__global__ void attn_kernel(const float* __restrict__ kernel_bank,
                            const float* __restrict__ attn_w,
                            const float* __restrict__ attn_b) {
    const int b = blockIdx.x;
    const int c = threadIdx.x;               // 128 threads
    __shared__ float red[128];
    __shared__ float logit[KB_];
    __shared__ float attn[KB_];

    float p = g_pooled[b * C_ + c];
    for (int k = 0; k < KB_; k++) {
        red[c] = p * attn_w[k * C_ + c];
        __syncthreads();
        for (int st = 64; st > 0; st >>= 1) {
            if (c < st) red[c] += red[c + st];
            __syncthreads();
        }
        if (c == 0) logit[k] = red[0] + attn_b[k];
        __syncthreads();
    }
    if (c == 0) {
        float mx = logit[0];
        for (int k = 1; k < KB_; k++) mx = fmaxf(mx, logit[k]);
        float s = 0.f;
        for (int k = 0; k < KB_; k++) { attn[k] = expf(logit[k] - mx); s += attn[k]; }
        float inv = 1.f / s;
        for (int k = 0; k < KB_; k++) attn[k] *= inv;
    }
    __syncthreads();
    float a0 = attn[0], a1 = attn[1], a2 = attn[2], a3 = attn[3];
#pragma unroll
    for (int ij = 0; ij < 9; ij++) {
        float s = a0 * kernel_bank[(0 * C_ + c) * 9 + ij]
                + a1 * kernel_bank[(1 * C_ + c) * 9 + ij]
                + a2 * kernel_bank[(2 * C_ + c) * 9 + ij]
                + a3 * kernel_bank[(3 * C_ + c) * 9 + ij];
        g_dynk[(b * C_ + c) * 9 + ij] = s;
    }
}

// ---------------------------------------------------------------------------
// Kernel 2b: transpose pw_w [OC, C] -> g_pwT [C, OC]
// ---------------------------------------------------------------------------
__global__ void transpose_pw(const float* __restrict__ pw_w) {
    const int c = blockIdx.x;                // 128 blocks
    const int o = threadIdx.x;               // 128 threads
    g_pwT[c * OC_ + o] = pw_w[o * C_ + c];
}

// ---------------------------------------------------------------------------
// Kernel 3: fused depthwise 3x3 (dynamic kernel) + pointwise 1x1 GEMM.
// Grid: (W/128, H, B). Block: 256 threads.
// Per CTA: 128 pixels (one half-row) x 128 output channels, K=128 input ch.
// K processed in chunks of 16: stage x halo -> compute dw tile A[16][128] ->
// GEMM with pwT panel B[16][128]. 8x8 register microtiles, f32x2 FMAs.
// ---------------------------------------------------------------------------
__global__ __launch_bounds__(256, 2)
void fused_kernel(const float* __restrict__ x,
                  const float* __restrict__ pw_b,
                  float* __restrict__ out) {
    const int t  = threadIdx.x;
    const int tx = t & 15;                   // n-dim (output channel) group
    const int ty = t >> 4;                   // m-dim (pixel) group
    const int w0 = blockIdx.x * 128;
    const int h  = blockIdx.y;
    const int b  = blockIdx.z;

    __shared__ float xs[16][3][132];         // 16 ch x 3 rows x (128+2 halo, padded)
    __shared__ float As[16][128];            // depthwise results: [kc][pixel]
    __shared__ float Bs[16][128];            // pwT panel:         [kc][oc]
    __shared__ float dk[128][9];             // dynamic kernels for this batch

    // load dynamic kernel for this batch (1152 floats)
    for (int i = t; i < C_ * 9; i += 256)
        (&dk[0][0])[i] = g_dynk[b * C_ * 9 + i];

    unsigned long long acc[8][4];
#pragma unroll
    for (int i = 0; i < 8; i++)
#pragma unroll
        for (int jp = 0; jp < 4; jp++) acc[i][jp] = 0ULL;

    for (int c0 = 0; c0 < C_; c0 += 16) {
        __syncthreads();   // previous GEMM done reading As/Bs (also covers dk init)

        // --- stage B panel: contiguous 2048 floats of pwT ---
        {
            const float4* src = reinterpret_cast<const float4*>(g_pwT + c0 * OC_);
            float4* dst = reinterpret_cast<float4*>(&Bs[0][0]);
            dst[t]       = src[t];
            dst[t + 256] = src[t + 256];
        }
        // --- stage x halo: 16 ch x 3 rows x 130 cols (zero-padded) ---
        for (int idx = t; idx < 16 * 390; idx += 256) {
            int c   = idx / 390;
            int rem = idx - c * 390;
            int r   = rem / 130;
            int col = rem - r * 130;
            int hh = h + r - 1;
            int ww = w0 + col - 1;
            float v = 0.f;
            if ((unsigned)hh < (unsigned)H_ && (unsigned)ww < (unsigned)W_)
                v = x[(((size_t)(b * C_ + c0 + c)) * H_ + hh) * W_ + ww];
            xs[c][r][col] = v;
        }
        __syncthreads();

        // --- depthwise 3x3 into As[kc][m] ---
#pragma unroll
        for (int it = 0; it < 8; it++) {
            int idx = t + it * 256;
            int c = idx >> 7;
            int m = idx & 127;
            const float* dkc = dk[c0 + c];
            float s = 0.f;
#pragma unroll
            for (int r = 0; r < 3; r++)
#pragma unroll
                for (int j = 0; j < 3; j++)
                    s = fmaf(dkc[r * 3 + j], xs[c][r][m + j], s);
            As[c][m] = s;
        }
        __syncthreads();

        // --- GEMM accumulate: 16 k-steps ---
#pragma unroll
        for (int kc = 0; kc < 16; kc++) {
            float4 a0 = *reinterpret_cast<const float4*>(&As[kc][ty * 8]);
            float4 a1 = *reinterpret_cast<const float4*>(&As[kc][ty * 8 + 4]);
            ulonglong2 bv0 = *reinterpret_cast<const ulonglong2*>(&Bs[kc][tx * 8]);
            ulonglong2 bv1 = *reinterpret_cast<const ulonglong2*>(&Bs[kc][tx * 8 + 4]);
            unsigned long long bb[4] = {bv0.x, bv0.y, bv1.x, bv1.y};
            float av[8] = {a0.x, a0.y, a0.z, a0.w, a1.x, a1.y, a1.z, a1.w};
#pragma unroll
            for (int i = 0; i < 8; i++) {
                unsigned long long aa;
                asm("mov.b64 %0, {%1, %1};" : "=l"(aa) : "f"(av[i]));
#pragma unroll
                for (int jp = 0; jp < 4; jp++)
                    asm("fma.rn.f32x2 %0, %1, %2, %0;"
                        : "+l"(acc[i][jp]) : "l"(aa), "l"(bb[jp]));
            }
        }
    }

    // --- epilogue: add bias, store 8x8 microtile (32B contiguous per o) ---
#pragma unroll
    for (int j = 0; j < 8; j++) {
        int o = tx * 8 + j;
        float bias = __ldg(pw_b + o);
        float v[8];
#pragma unroll
        for (int i = 0; i < 8; i++) {
            unsigned long long pair = acc[i][j >> 1];
            unsigned int bits = (j & 1) ? (unsigned int)(pair >> 32)
                                        : (unsigned int)(pair & 0xffffffffu);
            v[i] = __uint_as_float(bits) + bias;
        }
        size_t base = (((size_t)(b * OC_ + o)) * H_ + h) * W_ + w0 + ty * 8;
        *reinterpret_cast<float4*>(out + base)     = make_float4(v[0], v[1], v[2], v[3]);
        *reinterpret_cast<float4*>(out + base + 4) = make_float4(v[4], v[5], v[6], v[7]);
    }
}

// ---------------------------------------------------------------------------
extern "C" void kernel_launch(void* const* d_in, const int* in_sizes, int n_in,
                              void* d_out, int out_size) {
    const float* x           = (const float*)d_in[0];
    const float* kernel_bank = (const float*)d_in[1];
    const float* attn_w      = (const float*)d_in[2];
    const float* attn_b      = (const float*)d_in[3];
    const float* pw_w        = (const float*)d_in[4];
    const float* pw_b        = (const float*)d_in[5];
    float* out               = (float*)d_out;

    pool_kernel<<<B_ * C_, 256>>>(x);
    attn_kernel<<<B_, 128>>>(kernel_bank, attn_w, attn_b);
    transpose_pw<<<C_, OC_>>>(pw_w);
    fused_kernel<<<dim3(W_ / 128, H_, B_), 256>>>(x, pw_b, out);
}

// round 3
// speedup vs baseline: 1.6150x; 1.6150x over previous
#include <cuda_runtime.h>
#include <cstdint>

// Problem constants
#define B_  8
#define C_  128
#define H_  256
#define W_  256
#define KB_ 4
#define OC_ 128

// Scratch (static device arrays; no allocation)
__device__ float g_pooled[B_ * C_];          // [B, C] GAP results
__device__ float g_dynk[B_ * C_ * 9];        // [B, C, 3, 3] dynamic depthwise kernels
__device__ float g_pwT[C_ * OC_];            // pw_w transposed: [C, OC]

// ---------------------------------------------------------------------------
// Kernel 1: global average pool. One block per (b,c) plane of 65536 floats.
// ---------------------------------------------------------------------------
__global__ void pool_kernel(const float* __restrict__ x) {
    const int plane = blockIdx.x;            // b*C + c
    const int t = threadIdx.x;               // 256 threads
    const float4* p = reinterpret_cast<const float4*>(x + (size_t)plane * (H_ * W_));
    float s = 0.f;
#pragma unroll 8
    for (int it = 0; it < 64; it++) {
        float4 v = p[it * 256 + t];
        s += (v.x + v.y) + (v.z + v.w);
    }
    __shared__ float red[256];
    red[t] = s;
    __syncthreads();
    for (int st = 128; st > 0; st >>= 1) {
        if (t < st) red[t] += red[t + st];
        __syncthreads();
    }
    if (t == 0) g_pooled[plane] = red[0] * (1.f / (H_ * W_));
}

// ---------------------------------------------------------------------------
// Kernel 2: attention -> softmax -> dynamic depthwise kernel per (b,c).
// ---------------------------------------------------------------------------
__global__ void attn_kernel(const float* __restrict__ kernel_bank,
                            const float* __restrict__ attn_w,
                            const float* __restrict__ attn_b) {
    const int b = blockIdx.x;
    const int c = threadIdx.x;               // 128 threads
    __shared__ float red[128];
    __shared__ float logit[KB_];
    __shared__ float attn[KB_];

    float p = g_pooled[b * C_ + c];
    for (int k = 0; k < KB_; k++) {
        red[c] = p * attn_w[k * C_ + c];
        __syncthreads();
        for (int st = 64; st > 0; st >>= 1) {
            if (c < st) red[c] += red[c + st];
            __syncthreads();
        }
        if (c == 0) logit[k] = red[0] + attn_b[k];
        __syncthreads();
    }
    if (c == 0) {
        float mx = logit[0];
        for (int k = 1; k < KB_; k++) mx = fmaxf(mx, logit[k]);
        float s = 0.f;
        for (int k = 0; k < KB_; k++) { attn[k] = expf(logit[k] - mx); s += attn[k]; }
        float inv = 1.f / s;
        for (int k = 0; k < KB_; k++) attn[k] *= inv;
    }
    __syncthreads();
    float a0 = attn[0], a1 = attn[1], a2 = attn[2], a3 = attn[3];
#pragma unroll
    for (int ij = 0; ij < 9; ij++) {
        float s = a0 * kernel_bank[(0 * C_ + c) * 9 + ij]
                + a1 * kernel_bank[(1 * C_ + c) * 9 + ij]
                + a2 * kernel_bank[(2 * C_ + c) * 9 + ij]
                + a3 * kernel_bank[(3 * C_ + c) * 9 + ij];
        g_dynk[(b * C_ + c) * 9 + ij] = s;
    }
}

// ---------------------------------------------------------------------------
// Kernel 2b: transpose pw_w [OC, C] -> g_pwT [C, OC]
// ---------------------------------------------------------------------------
__global__ void transpose_pw(const float* __restrict__ pw_w) {
    const int c = blockIdx.x;
    const int o = threadIdx.x;
    g_pwT[c * OC_ + o] = pw_w[o * C_ + c];
}

// ---------------------------------------------------------------------------
// Fused depthwise 3x3 + pointwise GEMM, cp.async double-buffered pipeline.
// Grid: (W/128, H, B). Block 256.
// Shared layout (dynamic):
//   xs:  2 bufs x 16 ch x 3 rows x 136 floats
//        smem col s holds global col (w0 + s - 4): interior cols 4..131,
//        left halo col 3 (w0-1), right halo col 132 (w0+128).
//   Bs:  2 bufs x 16 x 128
//   As:  16 x 128
//   dk:  128 x 9
// ---------------------------------------------------------------------------
#define XS_ROW   136
#define XS_BUF   (16 * 3 * XS_ROW)          // 6528 floats per buffer
#define XS_TOTAL (2 * XS_BUF)               // 13056
#define BS_BUF   (16 * 128)                 // 2048
#define BS_TOTAL (2 * BS_BUF)               // 4096
#define AS_SIZE  (16 * 128)                 // 2048
#define DK_SIZE  (128 * 9)                  // 1152
#define SMEM_FLOATS (XS_TOTAL + BS_TOTAL + AS_SIZE + DK_SIZE)   // 20352 -> 81408 B

__device__ __forceinline__ void stage_chunk(const float* __restrict__ x,
                                            int b, int c0, int h, int w0,
                                            float* xsbuf, float* bsbuf, int t) {
    // B panel: 2048 contiguous floats of pwT
    {
        const float* src = g_pwT + c0 * OC_;
        unsigned int da = (unsigned int)__cvta_generic_to_shared(bsbuf);
        asm volatile("cp.async.cg.shared.global [%0], [%1], 16;\n"
                     :: "r"(da + t * 16u), "l"(src + t * 4));
        asm volatile("cp.async.cg.shared.global [%0], [%1], 16;\n"
                     :: "r"(da + (t + 256) * 16u), "l"(src + (t + 256) * 4));
    }
    // x interior: 16 ch x 3 rows x 32 float4 = 1536 ops, 6 per thread
#pragma unroll
    for (int i = 0; i < 6; i++) {
        int idx = t + i * 256;
        int c   = idx / 96;
        int rem = idx - c * 96;
        int r   = rem >> 5;
        int q   = rem & 31;
        int hh  = h + r - 1;
        float* dst = xsbuf + (c * 3 + r) * XS_ROW + 4 + q * 4;
        if ((unsigned)hh < (unsigned)H_) {
            const float* src = x + (((size_t)(b * C_ + c0 + c)) * H_ + hh) * W_ + w0 + q * 4;
            unsigned int da = (unsigned int)__cvta_generic_to_shared(dst);
            asm volatile("cp.async.cg.shared.global [%0], [%1], 16;\n"
                         :: "r"(da), "l"(src));
        } else {
            *reinterpret_cast<float4*>(dst) = make_float4(0.f, 0.f, 0.f, 0.f);
        }
    }
    // x halo columns: 16 ch x 3 rows x 2 sides = 96 scalars
    if (t < 96) {
        int c    = t / 6;
        int rem  = t - c * 6;
        int r    = rem >> 1;
        int side = rem & 1;
        int hh   = h + r - 1;
        int ww   = side ? (w0 + 128) : (w0 - 1);
        int col  = side ? 132 : 3;
        float* dst = xsbuf + (c * 3 + r) * XS_ROW + col;
        if ((unsigned)hh < (unsigned)H_ && (unsigned)ww < (unsigned)W_) {
            const float* src = x + (((size_t)(b * C_ + c0 + c)) * H_ + hh) * W_ + ww;
            unsigned int da = (unsigned int)__cvta_generic_to_shared(dst);
            asm volatile("cp.async.ca.shared.global [%0], [%1], 4;\n"
                         :: "r"(da), "l"(src));
        } else {
            *dst = 0.f;
        }
    }
    asm volatile("cp.async.commit_group;\n" ::: "memory");
}

__global__ __launch_bounds__(256, 2)
void fused_kernel(const float* __restrict__ x,
                  const float* __restrict__ pw_b,
                  float* __restrict__ out) {
    extern __shared__ float smem[];
    float* xs = smem;                       // [2][16][3][136]
    float* Bs = smem + XS_TOTAL;            // [2][16][128]
    float* As = smem + XS_TOTAL + BS_TOTAL; // [16][128]
    float* dk = smem + XS_TOTAL + BS_TOTAL + AS_SIZE;   // [128][9]

    const int t  = threadIdx.x;
    const int tx = t & 15;
    const int ty = t >> 4;
    const int w0 = blockIdx.x * 128;
    const int h  = blockIdx.y;
    const int b  = blockIdx.z;

    // prologue: stage chunk 0, load dyn kernels
    stage_chunk(x, b, 0, h, w0, xs, Bs, t);
    for (int i = t; i < DK_SIZE; i += 256)
        dk[i] = g_dynk[b * DK_SIZE + i];

    unsigned long long acc[8][4];
#pragma unroll
    for (int i = 0; i < 8; i++)
#pragma unroll
        for (int jp = 0; jp < 4; jp++) acc[i][jp] = 0ULL;

    const int dw_c  = t >> 4;               // 0..15
    const int dw_m0 = (t & 15) << 3;        // 0..120

    for (int ci = 0; ci < 8; ci++) {
        const int buf = ci & 1;
        asm volatile("cp.async.wait_group 0;\n" ::: "memory");
        __syncthreads();    // chunk ci staged & visible; prev GEMM done with buf^1

        if (ci < 7)
            stage_chunk(x, b, (ci + 1) * 16, h, w0,
                        xs + (buf ^ 1) * XS_BUF, Bs + (buf ^ 1) * BS_BUF, t);

        // --- depthwise 3x3: 8 consecutive pixels per thread ---
        // pixel m taps smem cols m+3 .. m+5; v[i] = smem col dw_m0 + i
        {
            const float* dkc  = dk + (ci * 16 + dw_c) * 9;
            const float* rowb = xs + buf * XS_BUF + (dw_c * 3) * XS_ROW + dw_m0;
            float s[8];
#pragma unroll
            for (int j = 0; j < 8; j++) s[j] = 0.f;
#pragma unroll
            for (int r = 0; r < 3; r++) {
                const float* rp = rowb + r * XS_ROW;
                float4 q0 = *reinterpret_cast<const float4*>(rp);
                float4 q1 = *reinterpret_cast<const float4*>(rp + 4);
                float4 q2 = *reinterpret_cast<const float4*>(rp + 8);
                float4 q3 = *reinterpret_cast<const float4*>(rp + 12);
                float v[16] = {q0.x, q0.y, q0.z, q0.w,
                               q1.x, q1.y, q1.z, q1.w,
                               q2.x, q2.y, q2.z, q2.w,
                               q3.x, q3.y, q3.z, q3.w};
                float k0 = dkc[r * 3 + 0], k1 = dkc[r * 3 + 1], k2 = dkc[r * 3 + 2];
#pragma unroll
                for (int j = 0; j < 8; j++) {
                    s[j] = fmaf(k0, v[j + 3], s[j]);
                    s[j] = fmaf(k1, v[j + 4], s[j]);
                    s[j] = fmaf(k2, v[j + 5], s[j]);
                }
            }
            float* ap = As + dw_c * 128 + dw_m0;
            *reinterpret_cast<float4*>(ap)     = make_float4(s[0], s[1], s[2], s[3]);
            *reinterpret_cast<float4*>(ap + 4) = make_float4(s[4], s[5], s[6], s[7]);
        }
        __syncthreads();    // As ready

        // --- GEMM accumulate: 16 k-steps on As x Bs[buf] ---
        const float* bsb = Bs + buf * BS_BUF;
#pragma unroll
        for (int kc = 0; kc < 16; kc++) {
            float4 a0 = *reinterpret_cast<const float4*>(&As[kc * 128 + ty * 8]);
            float4 a1 = *reinterpret_cast<const float4*>(&As[kc * 128 + ty * 8 + 4]);
            ulonglong2 bv0 = *reinterpret_cast<const ulonglong2*>(&bsb[kc * 128 + tx * 8]);
            ulonglong2 bv1 = *reinterpret_cast<const ulonglong2*>(&bsb[kc * 128 + tx * 8 + 4]);
            unsigned long long bb[4] = {bv0.x, bv0.y, bv1.x, bv1.y};
            float av[8] = {a0.x, a0.y, a0.z, a0.w, a1.x, a1.y, a1.z, a1.w};
#pragma unroll
            for (int i = 0; i < 8; i++) {
                unsigned long long aa;
                asm("mov.b64 %0, {%1, %1};" : "=l"(aa) : "f"(av[i]));
#pragma unroll
                for (int jp = 0; jp < 4; jp++)
                    asm("fma.rn.f32x2 %0, %1, %2, %0;"
                        : "+l"(acc[i][jp]) : "l"(aa), "l"(bb[jp]));
            }
        }
    }

    // --- epilogue: add bias, store 8x8 microtile ---
#pragma unroll
    for (int j = 0; j < 8; j++) {
        int o = tx * 8 + j;
        float bias = __ldg(pw_b + o);
        float v[8];
#pragma unroll
        for (int i = 0; i < 8; i++) {
            unsigned long long pair = acc[i][j >> 1];
            unsigned int bits = (j & 1) ? (unsigned int)(pair >> 32)
                                        : (unsigned int)(pair & 0xffffffffu);
            v[i] = __uint_as_float(bits) + bias;
        }
        size_t base = (((size_t)(b * OC_ + o)) * H_ + h) * W_ + w0 + ty * 8;
        *reinterpret_cast<float4*>(out + base)     = make_float4(v[0], v[1], v[2], v[3]);
        *reinterpret_cast<float4*>(out + base + 4) = make_float4(v[4], v[5], v[6], v[7]);
    }
}

// ---------------------------------------------------------------------------
extern "C" void kernel_launch(void* const* d_in, const int* in_sizes, int n_in,
                              void* d_out, int out_size) {
    const float* x           = (const float*)d_in[0];
    const float* kernel_bank = (const float*)d_in[1];
    const float* attn_w      = (const float*)d_in[2];
    const float* attn_b      = (const float*)d_in[3];
    const float* pw_w        = (const float*)d_in[4];
    const float* pw_b        = (const float*)d_in[5];
    float* out               = (float*)d_out;

    static int smem_set = 0;
    if (!smem_set) {
        cudaFuncSetAttribute(fused_kernel,
                             cudaFuncAttributeMaxDynamicSharedMemorySize,
                             SMEM_FLOATS * 4);
        smem_set = 1;
    }

    pool_kernel<<<B_ * C_, 256>>>(x);
    attn_kernel<<<B_, 128>>>(kernel_bank, attn_w, attn_b);
    transpose_pw<<<C_, OC_>>>(pw_w);
    fused_kernel<<<dim3(W_ / 128, H_, B_), 256, SMEM_FLOATS * 4>>>(x, pw_b, out);
}

// round 5
// speedup vs baseline: 2.3382x; 1.4478x over previous
#include <cuda_runtime.h>
#include <cstdint>

// Problem constants
#define B_  8
#define C_  128
#define H_  256
#define W_  256
#define KB_ 4
#define OC_ 128

// Scratch (static device arrays; no allocation)
__device__ float g_pooled[B_ * C_];
__device__ float g_dynk[B_ * C_ * 9];
// pw_w pre-split (tf32 hi + fp32 residual lo) and pre-packed in
// mma.m16n8k8 B-fragment order: [ci(8)][s(2)][nt(16)][lane(32)][reg(2)]
__device__ float g_pwf_hi[8 * 2 * 16 * 32 * 2];   // 16384 floats
__device__ float g_pwf_lo[8 * 2 * 16 * 32 * 2];

// ---------------------------------------------------------------------------
// helpers
// ---------------------------------------------------------------------------
__device__ __forceinline__ uint32_t smem_u32(const void* p) {
    uint32_t a;
    asm("{ .reg .u64 t; cvta.to.shared.u64 t, %1; cvt.u32.u64 %0, t; }"
        : "=r"(a) : "l"(p));
    return a;
}
__device__ __forceinline__ uint32_t f2tf32(float v) {
    uint32_t r;
    asm("cvt.rna.tf32.f32 %0, %1;" : "=r"(r) : "f"(v));
    return r;
}
__device__ __forceinline__ void mma_tf32(float* d, const uint32_t* a,
                                         uint32_t b0, uint32_t b1) {
    asm volatile(
        "mma.sync.aligned.m16n8k8.row.col.f32.tf32.tf32.f32 "
        "{%0,%1,%2,%3}, {%4,%5,%6,%7}, {%8,%9}, {%0,%1,%2,%3};"
        : "+f"(d[0]), "+f"(d[1]), "+f"(d[2]), "+f"(d[3])
        : "r"(a[0]), "r"(a[1]), "r"(a[2]), "r"(a[3]), "r"(b0), "r"(b1));
}

// ---------------------------------------------------------------------------
// Kernel 1: global average pool
// ---------------------------------------------------------------------------
__global__ void pool_kernel(const float* __restrict__ x) {
    const int plane = blockIdx.x;
    const int t = threadIdx.x;
    const float4* p = reinterpret_cast<const float4*>(x + (size_t)plane * (H_ * W_));
    float s = 0.f;
#pragma unroll 8
    for (int it = 0; it < 64; it++) {
        float4 v = p[it * 256 + t];
        s += (v.x + v.y) + (v.z + v.w);
    }
    __shared__ float red[256];
    red[t] = s;
    __syncthreads();
    for (int st = 128; st > 0; st >>= 1) {
        if (t < st) red[t] += red[t + st];
        __syncthreads();
    }
    if (t == 0) g_pooled[plane] = red[0] * (1.f / (H_ * W_));
}

// ---------------------------------------------------------------------------
// Kernel 2: attention -> softmax -> dynamic depthwise kernel per (b,c)
// ---------------------------------------------------------------------------
__global__ void attn_kernel(const float* __restrict__ kernel_bank,
                            const float* __restrict__ attn_w,
                            const float* __restrict__ attn_b) {
    const int b = blockIdx.x;
    const int c = threadIdx.x;               // 128 threads
    __shared__ float red[128];
    __shared__ float logit[KB_];
    __shared__ float attn[KB_];

    float p = g_pooled[b * C_ + c];
    for (int k = 0; k < KB_; k++) {
        red[c] = p * attn_w[k * C_ + c];
        __syncthreads();
        for (int st = 64; st > 0; st >>= 1) {
            if (c < st) red[c] += red[c + st];
            __syncthreads();
        }
        if (c == 0) logit[k] = red[0] + attn_b[k];
        __syncthreads();
    }
    if (c == 0) {
        float mx = logit[0];
        for (int k = 1; k < KB_; k++) mx = fmaxf(mx, logit[k]);
        float s = 0.f;
        for (int k = 0; k < KB_; k++) { attn[k] = expf(logit[k] - mx); s += attn[k]; }
        float inv = 1.f / s;
        for (int k = 0; k < KB_; k++) attn[k] *= inv;
    }
    __syncthreads();
    float a0 = attn[0], a1 = attn[1], a2 = attn[2], a3 = attn[3];
#pragma unroll
    for (int ij = 0; ij < 9; ij++) {
        float s = a0 * kernel_bank[(0 * C_ + c) * 9 + ij]
                + a1 * kernel_bank[(1 * C_ + c) * 9 + ij]
                + a2 * kernel_bank[(2 * C_ + c) * 9 + ij]
                + a3 * kernel_bank[(3 * C_ + c) * 9 + ij];
        g_dynk[(b * C_ + c) * 9 + ij] = s;
    }
}

// ---------------------------------------------------------------------------
// Kernel 2b: split pw_w into tf32 hi + residual lo, packed in B-fragment order.
// B frag (k8 x n8): b0 = B[k = tig][n = lane>>2], b1 = B[tig+4][lane>>2].
// ---------------------------------------------------------------------------
__global__ void split_pw_frag(const float* __restrict__ pw_w) {
    int idx = blockIdx.x * 256 + threadIdx.x;   // 0..8191 over (ci,s,nt,lane)
    if (idx >= 8192) return;
    int lane = idx & 31;
    int nt   = (idx >> 5) & 15;
    int s    = (idx >> 9) & 1;
    int ci   = idx >> 10;
    int o = nt * 8 + (lane >> 2);
    int kb = ci * 16 + s * 8 + (lane & 3);
#pragma unroll
    for (int r = 0; r < 2; r++) {
        float v = pw_w[o * C_ + kb + r * 4];
        float hi = __uint_as_float(f2tf32(v));
        g_pwf_hi[idx * 2 + r] = hi;
        g_pwf_lo[idx * 2 + r] = v - hi;
    }
}

// ---------------------------------------------------------------------------
// Fused dw 3x3 + mma.sync tf32 GEMM (3xTF32 split for fp32 accuracy).
// Grid (W/128, H, B), 256 threads, 2 CTAs/SM.
// Smem (floats):
//   As_hi [0,2048)        A fragments (128 m x 16 k), hi
//   As_lo [2048,4096)     lo residuals
//   Bs    [4096,12288)    2 bufs x (hi 2048 + lo 2048)
//   xs    [12288,25728)   2 bufs x 16ch x 3rows x 140
//   dk    [25728,26880)
// ---------------------------------------------------------------------------
#define XS_ROW   140
#define XS_FLTS  (16 * 3 * XS_ROW)          // 6720 per buffer
#define AS_HI_F  0
#define AS_LO_F  2048
#define BS_F     4096
#define XS_F     12288
#define DK_F     25728
#define SMEM_FLOATS 26880                    // 107520 bytes

__device__ __forceinline__ void stage_xs(const float* __restrict__ x,
                                         int b, int c0, int h, int w0,
                                         float* xf, int t) {
    // interior: 16 ch x 3 rows x 32 float4
#pragma unroll
    for (int i = 0; i < 6; i++) {
        int idx = t + i * 256;
        int c   = idx / 96;
        int rem = idx - c * 96;
        int r   = rem >> 5;
        int q   = rem & 31;
        int hh  = h + r - 1;
        float* dst = xf + (c * 3 + r) * XS_ROW + 4 + q * 4;
        if ((unsigned)hh < (unsigned)H_) {
            const float* src = x + (((size_t)(b * C_ + c0 + c)) * H_ + hh) * W_ + w0 + q * 4;
            asm volatile("cp.async.cg.shared.global [%0], [%1], 16;"
                         :: "r"(smem_u32(dst)), "l"(src));
        } else {
            *reinterpret_cast<float4*>(dst) = make_float4(0.f, 0.f, 0.f, 0.f);
        }
    }
    // halo columns
    if (t < 96) {
        int c    = t / 6;
        int rem  = t - c * 6;
        int r    = rem >> 1;
        int side = rem & 1;
        int hh   = h + r - 1;
        int ww   = side ? (w0 + 128) : (w0 - 1);
        int col  = side ? 132 : 3;
        float* dst = xf + (c * 3 + r) * XS_ROW + col;
        if ((unsigned)hh < (unsigned)H_ && (unsigned)ww < (unsigned)W_) {
            const float* src = x + (((size_t)(b * C_ + c0 + c)) * H_ + hh) * W_ + ww;
            asm volatile("cp.async.ca.shared.global [%0], [%1], 4;"
                         :: "r"(smem_u32(dst)), "l"(src));
        } else {
            *dst = 0.f;
        }
    }
}

__device__ __forceinline__ void stage_B(int ci, float* bsbuf, int t) {
    const float* sh = g_pwf_hi + ci * 2048;
    const float* sl = g_pwf_lo + ci * 2048;
    uint32_t dh = smem_u32(bsbuf);
    uint32_t dl = smem_u32(bsbuf + 2048);
#pragma unroll
    for (int i = 0; i < 2; i++) {
        int idx = t + i * 256;          // 512 x 16B per array
        asm volatile("cp.async.cg.shared.global [%0], [%1], 16;"
                     :: "r"(dh + idx * 16u), "l"(sh + idx * 4));
        asm volatile("cp.async.cg.shared.global [%0], [%1], 16;"
                     :: "r"(dl + idx * 16u), "l"(sl + idx * 4));
    }
}

__global__ __launch_bounds__(256, 2)
void fused_kernel(const float* __restrict__ x,
                  const float* __restrict__ pw_b,
                  float* __restrict__ out) {
    extern __shared__ float smem[];
    float* dk = smem + DK_F;

    const int t    = threadIdx.x;
    const int wid  = t >> 5;
    const int lane = t & 31;
    const int w0   = blockIdx.x * 128;
    const int h    = blockIdx.y;
    const int bb   = blockIdx.z;

    // dw thread mapping: channel kch = t&15, pixels m = (t>>4)*8 + j
    const int kch = t & 15;
    const int mg  = t >> 4;
    // A-fragment write coords for (m, k=kch):
    //   s=kch>>3, kk=kch&7, tig=kk&3, khigh=kk>>2; mt=m>>4, g=m&7, mhigh=(m>>3)&1
    //   lane' = g*4+tig, reg = khigh*2+mhigh
    const int s_w  = kch >> 3;
    const int kk_w = kch & 7;
    const int asbase = ((s_w * 8 + (mg >> 1)) * 32 + (kk_w & 3)) * 4
                     + ((kk_w >> 2) * 2) + (mg & 1);

    // GEMM warp tiling: 4 m-warps x 2 n-warps
    const int wm = wid & 3;
    const int wn = wid >> 2;

    // prologue
    stage_xs(x, bb, 0, h, w0, smem + XS_F, t);
    stage_B(0, smem + BS_F, t);
    asm volatile("cp.async.commit_group;" ::: "memory");
    for (int i = t; i < C_ * 9; i += 256)
        dk[i] = g_dynk[bb * C_ * 9 + i];

    float acc[2][8][4];
#pragma unroll
    for (int i = 0; i < 2; i++)
#pragma unroll
        for (int j = 0; j < 8; j++)
#pragma unroll
            for (int k = 0; k < 4; k++) acc[i][j][k] = 0.f;

    for (int ci = 0; ci < 8; ci++) {
        const int buf = ci & 1;
        asm volatile("cp.async.wait_group 0;" ::: "memory");
        __syncthreads();   // chunk ci staged; all warps done with As & Bs[buf^1]

        if (ci < 7) {
            stage_xs(x, bb, (ci + 1) * 16, h, w0, smem + XS_F + (buf ^ 1) * XS_FLTS, t);
            stage_B(ci + 1, smem + BS_F + (buf ^ 1) * 4096, t);
            asm volatile("cp.async.commit_group;" ::: "memory");
        }

        // --- depthwise 3x3 -> A fragments (hi/lo) ---
        {
            const float* dkc  = dk + (ci * 16 + kch) * 9;
            const float* rowb = smem + XS_F + buf * XS_FLTS + kch * 3 * XS_ROW + mg * 8;
            float sv[8];
#pragma unroll
            for (int j = 0; j < 8; j++) sv[j] = 0.f;
#pragma unroll
            for (int r = 0; r < 3; r++) {
                const float* rp = rowb + r * XS_ROW;
                float4 q0 = *reinterpret_cast<const float4*>(rp);
                float4 q1 = *reinterpret_cast<const float4*>(rp + 4);
                float4 q2 = *reinterpret_cast<const float4*>(rp + 8);
                float4 q3 = *reinterpret_cast<const float4*>(rp + 12);
                float v[16] = {q0.x, q0.y, q0.z, q0.w, q1.x, q1.y, q1.z, q1.w,
                               q2.x, q2.y, q2.z, q2.w, q3.x, q3.y, q3.z, q3.w};
                float k0 = dkc[r * 3 + 0], k1 = dkc[r * 3 + 1], k2 = dkc[r * 3 + 2];
#pragma unroll
                for (int j = 0; j < 8; j++) {
                    sv[j] = fmaf(k0, v[j + 3], sv[j]);
                    sv[j] = fmaf(k1, v[j + 4], sv[j]);
                    sv[j] = fmaf(k2, v[j + 5], sv[j]);
                }
            }
#pragma unroll
            for (int j = 0; j < 8; j++) {
                float hi = __uint_as_float(f2tf32(sv[j]));
                smem[AS_HI_F + asbase + j * 16] = hi;
                smem[AS_LO_F + asbase + j * 16] = sv[j] - hi;
            }
        }
        __syncthreads();   // A fragments ready

        // --- GEMM: 2 k8-steps, 3xTF32 split ---
        const float* bsb = smem + BS_F + buf * 4096;
#pragma unroll
        for (int s = 0; s < 2; s++) {
            uint4 ah[2], al[2];
#pragma unroll
            for (int mA = 0; mA < 2; mA++) {
                int mt = wm * 2 + mA;
                const float* ap = smem + AS_HI_F + ((s * 8 + mt) * 32 + lane) * 4;
                ah[mA] = *reinterpret_cast<const uint4*>(ap);
                al[mA] = *reinterpret_cast<const uint4*>(ap + 2048);
            }
#pragma unroll
            for (int ntl = 0; ntl < 8; ntl++) {
                int nt = wn * 8 + ntl;
                const float* bp = bsb + ((s * 16 + nt) * 32 + lane) * 2;
                uint2 bh = *reinterpret_cast<const uint2*>(bp);
                uint2 bl = *reinterpret_cast<const uint2*>(bp + 2048);
#pragma unroll
                for (int mA = 0; mA < 2; mA++) {
                    mma_tf32(acc[mA][ntl], reinterpret_cast<uint32_t*>(&ah[mA]),
                             bh.x, bh.y);
                    mma_tf32(acc[mA][ntl], reinterpret_cast<uint32_t*>(&al[mA]),
                             bh.x, bh.y);
                    mma_tf32(acc[mA][ntl], reinterpret_cast<uint32_t*>(&ah[mA]),
                             bl.x, bl.y);
                }
            }
        }
    }

    // --- epilogue: D fragment (m16n8): c0=(g,2tig) c1=(g,2tig+1) c2/c3 at g+8 ---
    const int g   = lane >> 2;
    const int tig = lane & 3;
#pragma unroll
    for (int mA = 0; mA < 2; mA++) {
        int mbase = wm * 32 + mA * 16;
#pragma unroll
        for (int ntl = 0; ntl < 8; ntl++) {
            int o = wn * 64 + ntl * 8 + 2 * tig;
            float b0v = __ldg(pw_b + o);
            float b1v = __ldg(pw_b + o + 1);
            size_t r0 = (((size_t)(bb * OC_ + o)) * H_ + h) * W_ + w0;
            size_t r1 = r0 + (size_t)H_ * W_;
            const float* a4 = acc[mA][ntl];
            out[r0 + mbase + g]     = a4[0] + b0v;
            out[r1 + mbase + g]     = a4[1] + b1v;
            out[r0 + mbase + g + 8] = a4[2] + b0v;
            out[r1 + mbase + g + 8] = a4[3] + b1v;
        }
    }
}

// ---------------------------------------------------------------------------
extern "C" void kernel_launch(void* const* d_in, const int* in_sizes, int n_in,
                              void* d_out, int out_size) {
    const float* x           = (const float*)d_in[0];
    const float* kernel_bank = (const float*)d_in[1];
    const float* attn_w      = (const float*)d_in[2];
    const float* attn_b      = (const float*)d_in[3];
    const float* pw_w        = (const float*)d_in[4];
    const float* pw_b        = (const float*)d_in[5];
    float* out               = (float*)d_out;

    static int smem_set = 0;
    if (!smem_set) {
        cudaFuncSetAttribute(fused_kernel,
                             cudaFuncAttributeMaxDynamicSharedMemorySize,
                             SMEM_FLOATS * 4);
        smem_set = 1;
    }

    pool_kernel<<<B_ * C_, 256>>>(x);
    attn_kernel<<<B_, 128>>>(kernel_bank, attn_w, attn_b);
    split_pw_frag<<<32, 256>>>(pw_w);
    fused_kernel<<<dim3(W_ / 128, H_, B_), 256, SMEM_FLOATS * 4>>>(x, pw_b, out);
}

// round 6
// speedup vs baseline: 2.8123x; 1.2028x over previous
#include <cuda_runtime.h>
#include <cuda_bf16.h>
#include <cstdint>

// Problem constants
#define B_  8
#define C_  128
#define H_  256
#define W_  256
#define KB_ 4
#define OC_ 128

// Scratch (static device arrays; no allocation)
__device__ float g_pooled[B_ * C_];
__device__ float g_dynk[B_ * C_ * 9];
// pw_w split to bf16 hi + bf16 residual lo, packed in m16n8k16 B-fragment
// order: [ci(8)][nt(16)][lane(32)][4 words: bh0, bh1, bl0, bl1]
__device__ uint32_t g_pwf[8 * 16 * 32 * 4];        // 16384 u32

// ---------------------------------------------------------------------------
// helpers
// ---------------------------------------------------------------------------
__device__ __forceinline__ uint32_t smem_u32(const void* p) {
    uint32_t a;
    asm("{ .reg .u64 t; cvta.to.shared.u64 t, %1; cvt.u32.u64 %0, t; }"
        : "=r"(a) : "l"(p));
    return a;
}
__device__ __forceinline__ void mma_bf16(float* d, const uint32_t* a,
                                         uint32_t b0, uint32_t b1) {
    asm volatile(
        "mma.sync.aligned.m16n8k16.row.col.f32.bf16.bf16.f32 "
        "{%0,%1,%2,%3}, {%4,%5,%6,%7}, {%8,%9}, {%0,%1,%2,%3};"
        : "+f"(d[0]), "+f"(d[1]), "+f"(d[2]), "+f"(d[3])
        : "r"(a[0]), "r"(a[1]), "r"(a[2]), "r"(a[3]), "r"(b0), "r"(b1));
}
// split float into bf16 hi bits + bf16 residual bits
__device__ __forceinline__ uint32_t split_bf16_pair(float v) {
    __nv_bfloat16 h = __float2bfloat16_rn(v);
    float hif = __bfloat162float(h);
    __nv_bfloat16 l = __float2bfloat16_rn(v - hif);
    return (uint32_t)__bfloat16_as_ushort(h)
         | ((uint32_t)__bfloat16_as_ushort(l) << 16);
}

// ---------------------------------------------------------------------------
// Kernel 1: global average pool
// ---------------------------------------------------------------------------
__global__ void pool_kernel(const float* __restrict__ x) {
    const int plane = blockIdx.x;
    const int t = threadIdx.x;
    const float4* p = reinterpret_cast<const float4*>(x + (size_t)plane * (H_ * W_));
    float s = 0.f;
#pragma unroll 8
    for (int it = 0; it < 64; it++) {
        float4 v = p[it * 256 + t];
        s += (v.x + v.y) + (v.z + v.w);
    }
    __shared__ float red[256];
    red[t] = s;
    __syncthreads();
    for (int st = 128; st > 0; st >>= 1) {
        if (t < st) red[t] += red[t + st];
        __syncthreads();
    }
    if (t == 0) g_pooled[plane] = red[0] * (1.f / (H_ * W_));
}

// ---------------------------------------------------------------------------
// Kernel 2: attention -> softmax -> dynamic depthwise kernel per (b,c)
// ---------------------------------------------------------------------------
__global__ void attn_kernel(const float* __restrict__ kernel_bank,
                            const float* __restrict__ attn_w,
                            const float* __restrict__ attn_b) {
    const int b = blockIdx.x;
    const int c = threadIdx.x;               // 128 threads
    __shared__ float red[128];
    __shared__ float logit[KB_];
    __shared__ float attn[KB_];

    float p = g_pooled[b * C_ + c];
    for (int k = 0; k < KB_; k++) {
        red[c] = p * attn_w[k * C_ + c];
        __syncthreads();
        for (int st = 64; st > 0; st >>= 1) {
            if (c < st) red[c] += red[c + st];
            __syncthreads();
        }
        if (c == 0) logit[k] = red[0] + attn_b[k];
        __syncthreads();
    }
    if (c == 0) {
        float mx = logit[0];
        for (int k = 1; k < KB_; k++) mx = fmaxf(mx, logit[k]);
        float s = 0.f;
        for (int k = 0; k < KB_; k++) { attn[k] = expf(logit[k] - mx); s += attn[k]; }
        float inv = 1.f / s;
        for (int k = 0; k < KB_; k++) attn[k] *= inv;
    }
    __syncthreads();
    float a0 = attn[0], a1 = attn[1], a2 = attn[2], a3 = attn[3];
#pragma unroll
    for (int ij = 0; ij < 9; ij++) {
        float s = a0 * kernel_bank[(0 * C_ + c) * 9 + ij]
                + a1 * kernel_bank[(1 * C_ + c) * 9 + ij]
                + a2 * kernel_bank[(2 * C_ + c) * 9 + ij]
                + a3 * kernel_bank[(3 * C_ + c) * 9 + ij];
        g_dynk[(b * C_ + c) * 9 + ij] = s;
    }
}

// ---------------------------------------------------------------------------
// Kernel 2b: split pw_w to bf16 hi/lo, packed in B-fragment order.
// b0 = {B[k0+2tig], B[k0+2tig+1]}  b1 = {+8, +9}, low k in low 16 bits.
// ---------------------------------------------------------------------------
__global__ void split_pw_frag(const float* __restrict__ pw_w) {
    int idx = blockIdx.x * 256 + threadIdx.x;   // (ci, nt, lane)
    if (idx >= 4096) return;
    int lane = idx & 31;
    int nt   = (idx >> 5) & 15;
    int ci   = idx >> 9;
    int g = lane >> 2, tig = lane & 3;
    int o  = nt * 8 + g;
    int k0 = ci * 16 + 2 * tig;

    uint32_t p00 = split_bf16_pair(pw_w[o * C_ + k0]);       // {hi,lo}
    uint32_t p01 = split_bf16_pair(pw_w[o * C_ + k0 + 1]);
    uint32_t p10 = split_bf16_pair(pw_w[o * C_ + k0 + 8]);
    uint32_t p11 = split_bf16_pair(pw_w[o * C_ + k0 + 9]);

    g_pwf[idx * 4 + 0] = __byte_perm(p00, p01, 0x5410);      // bh0
    g_pwf[idx * 4 + 1] = __byte_perm(p10, p11, 0x5410);      // bh1
    g_pwf[idx * 4 + 2] = __byte_perm(p00, p01, 0x7632);      // bl0
    g_pwf[idx * 4 + 3] = __byte_perm(p10, p11, 0x7632);      // bl1
}

// ---------------------------------------------------------------------------
// Fused dw 3x3 + mma.sync bf16 GEMM (3xBF16 split).
// Grid (W/128, H, B), 256 threads, 2 CTAs/SM.
// Smem (floats):
//   A_hi  [0, 1024)          A fragments (128m x 16k) bf16x2 words, hi
//   A_lo  [1040, 2064)       (+16 float pad for bank offset)
//   Bs    [2080, 6176)       2 bufs x 2048 words {bh0,bh1,bl0,bl1}
//   xs    [6176, 19616)      2 bufs x 16ch x 3rows x 140
//   dk    [19616, 20768)
// ---------------------------------------------------------------------------
#define XS_ROW   140
#define XS_FLTS  (16 * 3 * XS_ROW)          // 6720 per buffer
#define AS_HI_F  0
#define AS_LO_F  1040
#define BS_F     2080
#define XS_F     6176
#define DK_F     19616
#define SMEM_FLOATS 20768                    // 83072 bytes

__device__ __forceinline__ void stage_xs(const float* __restrict__ x,
                                         int b, int c0, int h, int w0,
                                         float* xf, int t) {
#pragma unroll
    for (int i = 0; i < 6; i++) {
        int idx = t + i * 256;
        int c   = idx / 96;
        int rem = idx - c * 96;
        int r   = rem >> 5;
        int q   = rem & 31;
        int hh  = h + r - 1;
        float* dst = xf + (c * 3 + r) * XS_ROW + 4 + q * 4;
        if ((unsigned)hh < (unsigned)H_) {
            const float* src = x + (((size_t)(b * C_ + c0 + c)) * H_ + hh) * W_ + w0 + q * 4;
            asm volatile("cp.async.cg.shared.global [%0], [%1], 16;"
                         :: "r"(smem_u32(dst)), "l"(src));
        } else {
            *reinterpret_cast<float4*>(dst) = make_float4(0.f, 0.f, 0.f, 0.f);
        }
    }
    if (t < 96) {
        int c    = t / 6;
        int rem  = t - c * 6;
        int r    = rem >> 1;
        int side = rem & 1;
        int hh   = h + r - 1;
        int ww   = side ? (w0 + 128) : (w0 - 1);
        int col  = side ? 132 : 3;
        float* dst = xf + (c * 3 + r) * XS_ROW + col;
        if ((unsigned)hh < (unsigned)H_ && (unsigned)ww < (unsigned)W_) {
            const float* src = x + (((size_t)(b * C_ + c0 + c)) * H_ + hh) * W_ + ww;
            asm volatile("cp.async.ca.shared.global [%0], [%1], 4;"
                         :: "r"(smem_u32(dst)), "l"(src));
        } else {
            *dst = 0.f;
        }
    }
}

__device__ __forceinline__ void stage_B(int ci, float* bsbuf, int t) {
    const uint32_t* src = g_pwf + ci * 2048;
    uint32_t dh = smem_u32(bsbuf);
#pragma unroll
    for (int i = 0; i < 2; i++) {
        int idx = t + i * 256;          // 512 x 16B
        asm volatile("cp.async.cg.shared.global [%0], [%1], 16;"
                     :: "r"(dh + idx * 16u), "l"(src + idx * 4));
    }
}

__global__ __launch_bounds__(256, 2)
void fused_kernel(const float* __restrict__ x,
                  const float* __restrict__ pw_b,
                  float* __restrict__ out) {
    extern __shared__ float smem[];
    float* dk = smem + DK_F;

    const int t    = threadIdx.x;
    const int wid  = t >> 5;
    const int lane = t & 31;
    const int w0   = blockIdx.x * 128;
    const int h    = blockIdx.y;
    const int bb   = blockIdx.z;

    // dw mapping: channel kch = t&15, pixels m = mg*8 + j
    const int kch = t & 15;
    const int mg  = t >> 4;
    // A-fragment word coords for channel pair e=kch>>1, pixel m:
    //   mt = m>>4 = mg>>1, g = m&7 = j, mhigh = mg&1
    //   lane' = j*4 + (e&3), reg = (e>>2)*2 + mhigh
    const int wordbase = (mg >> 1) * 128 + ((kch >> 1) & 3) * 4
                       + (kch >> 3) * 2 + (mg & 1);
    float* abase = smem + ((kch & 1) ? AS_LO_F : AS_HI_F);
    const uint32_t psel = (kch & 1) ? 0x3276u : 0x5410u;

    // GEMM warp tiling: 4 m-warps x 2 n-warps
    const int wm = wid & 3;
    const int wn = wid >> 2;

    // prologue
    stage_xs(x, bb, 0, h, w0, smem + XS_F, t);
    stage_B(0, smem + BS_F, t);
    asm volatile("cp.async.commit_group;" ::: "memory");
    for (int i = t; i < C_ * 9; i += 256)
        dk[i] = g_dynk[bb * C_ * 9 + i];

    float acc[2][8][4];
#pragma unroll
    for (int i = 0; i < 2; i++)
#pragma unroll
        for (int j = 0; j < 8; j++)
#pragma unroll
            for (int k = 0; k < 4; k++) acc[i][j][k] = 0.f;

    for (int ci = 0; ci < 8; ci++) {
        const int buf = ci & 1;
        asm volatile("cp.async.wait_group 0;" ::: "memory");
        __syncthreads();   // chunk ci staged; all warps done with A & Bs[buf^1]

        if (ci < 7) {
            stage_xs(x, bb, (ci + 1) * 16, h, w0, smem + XS_F + (buf ^ 1) * XS_FLTS, t);
            stage_B(ci + 1, smem + BS_F + (buf ^ 1) * 2048, t);
            asm volatile("cp.async.commit_group;" ::: "memory");
        }

        // --- depthwise 3x3 -> bf16 hi/lo A fragments (pair via shfl) ---
        {
            const float* dkc  = dk + (ci * 16 + kch) * 9;
            const float* rowb = smem + XS_F + buf * XS_FLTS + kch * 3 * XS_ROW + mg * 8;
            float sv[8];
#pragma unroll
            for (int j = 0; j < 8; j++) sv[j] = 0.f;
#pragma unroll
            for (int r = 0; r < 3; r++) {
                const float* rp = rowb + r * XS_ROW;
                float4 q0 = *reinterpret_cast<const float4*>(rp);
                float4 q1 = *reinterpret_cast<const float4*>(rp + 4);
                float4 q2 = *reinterpret_cast<const float4*>(rp + 8);
                float4 q3 = *reinterpret_cast<const float4*>(rp + 12);
                float v[16] = {q0.x, q0.y, q0.z, q0.w, q1.x, q1.y, q1.z, q1.w,
                               q2.x, q2.y, q2.z, q2.w, q3.x, q3.y, q3.z, q3.w};
                float k0 = dkc[r * 3 + 0], k1 = dkc[r * 3 + 1], k2 = dkc[r * 3 + 2];
#pragma unroll
                for (int j = 0; j < 8; j++) {
                    sv[j] = fmaf(k0, v[j + 3], sv[j]);
                    sv[j] = fmaf(k1, v[j + 4], sv[j]);
                    sv[j] = fmaf(k2, v[j + 5], sv[j]);
                }
            }
#pragma unroll
            for (int j = 0; j < 8; j++) {
                uint32_t own = split_bf16_pair(sv[j]);                 // {hi,lo}
                uint32_t partner = __shfl_xor_sync(0xffffffffu, own, 1);
                uint32_t word = __byte_perm(own, partner, psel);
                abase[wordbase + j * 16] = __uint_as_float(word);
            }
        }
        __syncthreads();   // A fragments ready

        // --- GEMM: one k16 step, 3xBF16 split ---
        const float* bsb = smem + BS_F + buf * 2048;
        uint4 ah[2], al[2];
#pragma unroll
        for (int mA = 0; mA < 2; mA++) {
            int mt = wm * 2 + mA;
            int fi = (mt * 32 + lane) * 4;
            ah[mA] = *reinterpret_cast<const uint4*>(smem + AS_HI_F + fi);
            al[mA] = *reinterpret_cast<const uint4*>(smem + AS_LO_F + fi);
        }
#pragma unroll
        for (int ntl = 0; ntl < 8; ntl++) {
            int nt = wn * 8 + ntl;
            uint4 bv = *reinterpret_cast<const uint4*>(bsb + (nt * 32 + lane) * 4);
#pragma unroll
            for (int mA = 0; mA < 2; mA++) {
                mma_bf16(acc[mA][ntl], reinterpret_cast<uint32_t*>(&ah[mA]), bv.x, bv.y);
                mma_bf16(acc[mA][ntl], reinterpret_cast<uint32_t*>(&al[mA]), bv.x, bv.y);
                mma_bf16(acc[mA][ntl], reinterpret_cast<uint32_t*>(&ah[mA]), bv.z, bv.w);
            }
        }
    }

    // --- epilogue: D fragment scatter + bias ---
    const int g   = lane >> 2;
    const int tig = lane & 3;
#pragma unroll
    for (int mA = 0; mA < 2; mA++) {
        int mbase = wm * 32 + mA * 16;
#pragma unroll
        for (int ntl = 0; ntl < 8; ntl++) {
            int o = wn * 64 + ntl * 8 + 2 * tig;
            float b0v = __ldg(pw_b + o);
            float b1v = __ldg(pw_b + o + 1);
            size_t r0 = (((size_t)(bb * OC_ + o)) * H_ + h) * W_ + w0;
            size_t r1 = r0 + (size_t)H_ * W_;
            const float* a4 = acc[mA][ntl];
            out[r0 + mbase + g]     = a4[0] + b0v;
            out[r1 + mbase + g]     = a4[1] + b1v;
            out[r0 + mbase + g + 8] = a4[2] + b0v;
            out[r1 + mbase + g + 8] = a4[3] + b1v;
        }
    }
}

// ---------------------------------------------------------------------------
extern "C" void kernel_launch(void* const* d_in, const int* in_sizes, int n_in,
                              void* d_out, int out_size) {
    const float* x           = (const float*)d_in[0];
    const float* kernel_bank = (const float*)d_in[1];
    const float* attn_w      = (const float*)d_in[2];
    const float* attn_b      = (const float*)d_in[3];
    const float* pw_w        = (const float*)d_in[4];
    const float* pw_b        = (const float*)d_in[5];
    float* out               = (float*)d_out;

    static int smem_set = 0;
    if (!smem_set) {
        cudaFuncSetAttribute(fused_kernel,
                             cudaFuncAttributeMaxDynamicSharedMemorySize,
                             SMEM_FLOATS * 4);
        smem_set = 1;
    }

    pool_kernel<<<B_ * C_, 256>>>(x);
    attn_kernel<<<B_, 128>>>(kernel_bank, attn_w, attn_b);
    split_pw_frag<<<16, 256>>>(pw_w);
    fused_kernel<<<dim3(W_ / 128, H_, B_), 256, SMEM_FLOATS * 4>>>(x, pw_b, out);
}

// round 7
// speedup vs baseline: 2.8223x; 1.0035x over previous
#include <cuda_runtime.h>
#include <cuda_bf16.h>
#include <cstdint>

// Problem constants
#define B_  8
#define C_  128
#define H_  256
#define W_  256
#define KB_ 4
#define OC_ 128

// Scratch (static device arrays; no allocation)
__device__ float g_pooled[B_ * C_];
__device__ float g_dynk[B_ * C_ * 9];
// pw_w split to bf16 hi + bf16 residual lo, packed in m16n8k16 B-fragment
// order: [ci(8)][nt(16)][lane(32)][4 words: bh0, bh1, bl0, bl1]
__device__ uint32_t g_pwf[8 * 16 * 32 * 4];        // 16384 u32

// ---------------------------------------------------------------------------
// helpers
// ---------------------------------------------------------------------------
__device__ __forceinline__ uint32_t smem_u32(const void* p) {
    uint32_t a;
    asm("{ .reg .u64 t; cvta.to.shared.u64 t, %1; cvt.u32.u64 %0, t; }"
        : "=r"(a) : "l"(p));
    return a;
}
__device__ __forceinline__ void mma_bf16(float* d, const uint32_t* a,
                                         uint32_t b0, uint32_t b1) {
    asm volatile(
        "mma.sync.aligned.m16n8k16.row.col.f32.bf16.bf16.f32 "
        "{%0,%1,%2,%3}, {%4,%5,%6,%7}, {%8,%9}, {%0,%1,%2,%3};"
        : "+f"(d[0]), "+f"(d[1]), "+f"(d[2]), "+f"(d[3])
        : "r"(a[0]), "r"(a[1]), "r"(a[2]), "r"(a[3]), "r"(b0), "r"(b1));
}
// split float into bf16 hi bits + bf16 residual bits
__device__ __forceinline__ uint32_t split_bf16_pair(float v) {
    __nv_bfloat16 h = __float2bfloat16_rn(v);
    float hif = __bfloat162float(h);
    __nv_bfloat16 l = __float2bfloat16_rn(v - hif);
    return (uint32_t)__bfloat16_as_ushort(h)
         | ((uint32_t)__bfloat16_as_ushort(l) << 16);
}

// ---------------------------------------------------------------------------
// Kernel 1: global average pool
// ---------------------------------------------------------------------------
__global__ void pool_kernel(const float* __restrict__ x) {
    const int plane = blockIdx.x;
    const int t = threadIdx.x;
    const float4* p = reinterpret_cast<const float4*>(x + (size_t)plane * (H_ * W_));
    float s = 0.f;
#pragma unroll 8
    for (int it = 0; it < 64; it++) {
        float4 v = p[it * 256 + t];
        s += (v.x + v.y) + (v.z + v.w);
    }
    __shared__ float red[256];
    red[t] = s;
    __syncthreads();
    for (int st = 128; st > 0; st >>= 1) {
        if (t < st) red[t] += red[t + st];
        __syncthreads();
    }
    if (t == 0) g_pooled[plane] = red[0] * (1.f / (H_ * W_));
}

// ---------------------------------------------------------------------------
// Kernel 2: attention -> softmax -> dynamic depthwise kernel per (b,c)
// ---------------------------------------------------------------------------
__global__ void attn_kernel(const float* __restrict__ kernel_bank,
                            const float* __restrict__ attn_w,
                            const float* __restrict__ attn_b) {
    const int b = blockIdx.x;
    const int c = threadIdx.x;               // 128 threads
    __shared__ float red[128];
    __shared__ float logit[KB_];
    __shared__ float attn[KB_];

    float p = g_pooled[b * C_ + c];
    for (int k = 0; k < KB_; k++) {
        red[c] = p * attn_w[k * C_ + c];
        __syncthreads();
        for (int st = 64; st > 0; st >>= 1) {
            if (c < st) red[c] += red[c + st];
            __syncthreads();
        }
        if (c == 0) logit[k] = red[0] + attn_b[k];
        __syncthreads();
    }
    if (c == 0) {
        float mx = logit[0];
        for (int k = 1; k < KB_; k++) mx = fmaxf(mx, logit[k]);
        float s = 0.f;
        for (int k = 0; k < KB_; k++) { attn[k] = expf(logit[k] - mx); s += attn[k]; }
        float inv = 1.f / s;
        for (int k = 0; k < KB_; k++) attn[k] *= inv;
    }
    __syncthreads();
    float a0 = attn[0], a1 = attn[1], a2 = attn[2], a3 = attn[3];
#pragma unroll
    for (int ij = 0; ij < 9; ij++) {
        float s = a0 * kernel_bank[(0 * C_ + c) * 9 + ij]
                + a1 * kernel_bank[(1 * C_ + c) * 9 + ij]
                + a2 * kernel_bank[(2 * C_ + c) * 9 + ij]
                + a3 * kernel_bank[(3 * C_ + c) * 9 + ij];
        g_dynk[(b * C_ + c) * 9 + ij] = s;
    }
}

// ---------------------------------------------------------------------------
// Kernel 2b: split pw_w to bf16 hi/lo, packed in B-fragment order.
// ---------------------------------------------------------------------------
__global__ void split_pw_frag(const float* __restrict__ pw_w) {
    int idx = blockIdx.x * 256 + threadIdx.x;   // (ci, nt, lane)
    if (idx >= 4096) return;
    int lane = idx & 31;
    int nt   = (idx >> 5) & 15;
    int ci   = idx >> 9;
    int g = lane >> 2, tig = lane & 3;
    int o  = nt * 8 + g;
    int k0 = ci * 16 + 2 * tig;

    uint32_t p00 = split_bf16_pair(pw_w[o * C_ + k0]);       // {hi,lo}
    uint32_t p01 = split_bf16_pair(pw_w[o * C_ + k0 + 1]);
    uint32_t p10 = split_bf16_pair(pw_w[o * C_ + k0 + 8]);
    uint32_t p11 = split_bf16_pair(pw_w[o * C_ + k0 + 9]);

    g_pwf[idx * 4 + 0] = __byte_perm(p00, p01, 0x5410);      // bh0
    g_pwf[idx * 4 + 1] = __byte_perm(p10, p11, 0x5410);      // bh1
    g_pwf[idx * 4 + 2] = __byte_perm(p00, p01, 0x7632);      // bl0
    g_pwf[idx * 4 + 3] = __byte_perm(p10, p11, 0x7632);      // bl1
}

// ---------------------------------------------------------------------------
// Fused dw 3x3 + mma.sync bf16 GEMM (3xBF16 split), dw/GEMM software pipeline:
// per iteration: [stage ci+2] ; dw(ci+1) ; GEMM(ci) — ONE barrier per chunk,
// so fma-pipe (dw), tensor-pipe (MMA) and crossbar work overlap across warps.
// Grid (W/128, H, B), 256 threads, 2 CTAs/SM.
// Smem (floats):
//   As[2]  : each buf 2080 (hi 1024 @+0, lo 1024 @+1040, pads)
//   Bs[3]  : each 2048 words {bh0,bh1,bl0,bl1}
//   xs[2]  : 16ch x 3rows x 140
//   dk     : 1152
// ---------------------------------------------------------------------------
#define XS_ROW   140
#define XS_FLTS  (16 * 3 * XS_ROW)          // 6720 per buffer
#define AS_F     0
#define AS_STRIDE 2080
#define AS_LO_D  1040
#define BS_F     4160
#define XS_F     (BS_F + 3 * 2048)          // 10304
#define DK_F     (XS_F + 2 * XS_FLTS)       // 23744
#define SMEM_FLOATS (DK_F + 1152)           // 24896 -> 99584 B

__device__ __forceinline__ void stage_xs(const float* __restrict__ x,
                                         int b, int c0, int h, int w0,
                                         float* xf, int t) {
#pragma unroll
    for (int i = 0; i < 6; i++) {
        int idx = t + i * 256;
        int c   = idx / 96;
        int rem = idx - c * 96;
        int r   = rem >> 5;
        int q   = rem & 31;
        int hh  = h + r - 1;
        float* dst = xf + (c * 3 + r) * XS_ROW + 4 + q * 4;
        if ((unsigned)hh < (unsigned)H_) {
            const float* src = x + (((size_t)(b * C_ + c0 + c)) * H_ + hh) * W_ + w0 + q * 4;
            asm volatile("cp.async.cg.shared.global [%0], [%1], 16;"
                         :: "r"(smem_u32(dst)), "l"(src));
        } else {
            *reinterpret_cast<float4*>(dst) = make_float4(0.f, 0.f, 0.f, 0.f);
        }
    }
    if (t < 96) {
        int c    = t / 6;
        int rem  = t - c * 6;
        int r    = rem >> 1;
        int side = rem & 1;
        int hh   = h + r - 1;
        int ww   = side ? (w0 + 128) : (w0 - 1);
        int col  = side ? 132 : 3;
        float* dst = xf + (c * 3 + r) * XS_ROW + col;
        if ((unsigned)hh < (unsigned)H_ && (unsigned)ww < (unsigned)W_) {
            const float* src = x + (((size_t)(b * C_ + c0 + c)) * H_ + hh) * W_ + ww;
            asm volatile("cp.async.ca.shared.global [%0], [%1], 4;"
                         :: "r"(smem_u32(dst)), "l"(src));
        } else {
            *dst = 0.f;
        }
    }
}

__device__ __forceinline__ void stage_B(int ci, float* bsbuf, int t) {
    const uint32_t* src = g_pwf + ci * 2048;
    uint32_t dh = smem_u32(bsbuf);
#pragma unroll
    for (int i = 0; i < 2; i++) {
        int idx = t + i * 256;          // 512 x 16B
        asm volatile("cp.async.cg.shared.global [%0], [%1], 16;"
                     :: "r"(dh + idx * 16u), "l"(src + idx * 4));
    }
}

__global__ __launch_bounds__(256, 2)
void fused_kernel(const float* __restrict__ x,
                  const float* __restrict__ pw_b,
                  float* __restrict__ out) {
    extern __shared__ float smem[];
    float* dk = smem + DK_F;

    const int t    = threadIdx.x;
    const int wid  = t >> 5;
    const int lane = t & 31;
    const int w0   = blockIdx.x * 128;
    const int h    = blockIdx.y;
    const int bb   = blockIdx.z;

    // dw mapping: channel kch = t&15, pixels m = mg*8 + j
    const int kch = t & 15;
    const int mg  = t >> 4;
    const int wordbase = (mg >> 1) * 128 + ((kch >> 1) & 3) * 4
                       + (kch >> 3) * 2 + (mg & 1);
    const int a_lo_sel = (kch & 1) ? AS_LO_D : 0;
    const uint32_t psel = (kch & 1) ? 0x3276u : 0x5410u;

    // GEMM warp tiling: 4 m-warps x 2 n-warps
    const int wm = wid & 3;
    const int wn = wid >> 2;

    // prologue: stage chunk 0, drain, stage chunk 1, dw(0)
    stage_xs(x, bb, 0, h, w0, smem + XS_F, t);
    stage_B(0, smem + BS_F, t);
    asm volatile("cp.async.commit_group;" ::: "memory");
    for (int i = t; i < C_ * 9; i += 256)
        dk[i] = g_dynk[bb * C_ * 9 + i];

    float acc[2][8][4];
#pragma unroll
    for (int i = 0; i < 2; i++)
#pragma unroll
        for (int j = 0; j < 8; j++)
#pragma unroll
            for (int k = 0; k < 4; k++) acc[i][j][k] = 0.f;

    asm volatile("cp.async.wait_group 0;" ::: "memory");
    __syncthreads();
    stage_xs(x, bb, 16, h, w0, smem + XS_F + XS_FLTS, t);
    stage_B(1, smem + BS_F + 2048, t);
    asm volatile("cp.async.commit_group;" ::: "memory");

    // dw(0) -> As[0]
    {
        const float* dkc  = dk + kch * 9;
        const float* rowb = smem + XS_F + kch * 3 * XS_ROW + mg * 8;
        float sv[8];
#pragma unroll
        for (int j = 0; j < 8; j++) sv[j] = 0.f;
#pragma unroll
        for (int r = 0; r < 3; r++) {
            const float* rp = rowb + r * XS_ROW;
            float4 q0 = *reinterpret_cast<const float4*>(rp);
            float4 q1 = *reinterpret_cast<const float4*>(rp + 4);
            float4 q2 = *reinterpret_cast<const float4*>(rp + 8);
            float4 q3 = *reinterpret_cast<const float4*>(rp + 12);
            float v[16] = {q0.x, q0.y, q0.z, q0.w, q1.x, q1.y, q1.z, q1.w,
                           q2.x, q2.y, q2.z, q2.w, q3.x, q3.y, q3.z, q3.w};
            float k0 = dkc[r * 3 + 0], k1 = dkc[r * 3 + 1], k2 = dkc[r * 3 + 2];
#pragma unroll
            for (int j = 0; j < 8; j++) {
                sv[j] = fmaf(k0, v[j + 3], sv[j]);
                sv[j] = fmaf(k1, v[j + 4], sv[j]);
                sv[j] = fmaf(k2, v[j + 5], sv[j]);
            }
        }
        float* abase = smem + AS_F + a_lo_sel;
#pragma unroll
        for (int j = 0; j < 8; j++) {
            uint32_t own = split_bf16_pair(sv[j]);
            uint32_t partner = __shfl_xor_sync(0xffffffffu, own, 1);
            abase[wordbase + j * 16] = __uint_as_float(__byte_perm(own, partner, psel));
        }
    }

#pragma unroll 1
    for (int ci = 0; ci < 8; ci++) {
        if (ci < 7)
            asm volatile("cp.async.wait_group 0;" ::: "memory");
        __syncthreads();   // dw(ci) visible; GEMM(ci-1) done with As[(ci+1)&1], Bs[(ci-1)%3]

        if (ci < 6) {
            stage_xs(x, bb, (ci + 2) * 16, h, w0, smem + XS_F + (ci & 1) * XS_FLTS, t);
            stage_B(ci + 2, smem + BS_F + ((ci + 2) % 3) * 2048, t);
            asm volatile("cp.async.commit_group;" ::: "memory");
        }

        // --- dw(ci+1) -> As[(ci+1)&1]  (overlaps with GEMM(ci) across warps) ---
        if (ci < 7) {
            const int cj = ci + 1;
            const float* dkc  = dk + (cj * 16 + kch) * 9;
            const float* rowb = smem + XS_F + (cj & 1) * XS_FLTS
                              + kch * 3 * XS_ROW + mg * 8;
            float sv[8];
#pragma unroll
            for (int j = 0; j < 8; j++) sv[j] = 0.f;
#pragma unroll
            for (int r = 0; r < 3; r++) {
                const float* rp = rowb + r * XS_ROW;
                float4 q0 = *reinterpret_cast<const float4*>(rp);
                float4 q1 = *reinterpret_cast<const float4*>(rp + 4);
                float4 q2 = *reinterpret_cast<const float4*>(rp + 8);
                float4 q3 = *reinterpret_cast<const float4*>(rp + 12);
                float v[16] = {q0.x, q0.y, q0.z, q0.w, q1.x, q1.y, q1.z, q1.w,
                               q2.x, q2.y, q2.z, q2.w, q3.x, q3.y, q3.z, q3.w};
                float k0 = dkc[r * 3 + 0], k1 = dkc[r * 3 + 1], k2 = dkc[r * 3 + 2];
#pragma unroll
                for (int j = 0; j < 8; j++) {
                    sv[j] = fmaf(k0, v[j + 3], sv[j]);
                    sv[j] = fmaf(k1, v[j + 4], sv[j]);
                    sv[j] = fmaf(k2, v[j + 5], sv[j]);
                }
            }
            float* abase = smem + AS_F + (cj & 1) * AS_STRIDE + a_lo_sel;
#pragma unroll
            for (int j = 0; j < 8; j++) {
                uint32_t own = split_bf16_pair(sv[j]);
                uint32_t partner = __shfl_xor_sync(0xffffffffu, own, 1);
                abase[wordbase + j * 16] =
                    __uint_as_float(__byte_perm(own, partner, psel));
            }
        }

        // --- GEMM(ci): one k16 step, 3xBF16 split ---
        {
            const float* asb = smem + AS_F + (ci & 1) * AS_STRIDE;
            const float* bsb = smem + BS_F + (ci % 3) * 2048;
            uint4 ah[2], al[2];
#pragma unroll
            for (int mA = 0; mA < 2; mA++) {
                int fi = ((wm * 2 + mA) * 32 + lane) * 4;
                ah[mA] = *reinterpret_cast<const uint4*>(asb + fi);
                al[mA] = *reinterpret_cast<const uint4*>(asb + AS_LO_D + fi);
            }
#pragma unroll
            for (int ntl = 0; ntl < 8; ntl++) {
                int nt = wn * 8 + ntl;
                uint4 bv = *reinterpret_cast<const uint4*>(bsb + (nt * 32 + lane) * 4);
#pragma unroll
                for (int mA = 0; mA < 2; mA++) {
                    mma_bf16(acc[mA][ntl], reinterpret_cast<uint32_t*>(&ah[mA]),
                             bv.x, bv.y);
                    mma_bf16(acc[mA][ntl], reinterpret_cast<uint32_t*>(&al[mA]),
                             bv.x, bv.y);
                    mma_bf16(acc[mA][ntl], reinterpret_cast<uint32_t*>(&ah[mA]),
                             bv.z, bv.w);
                }
            }
        }
    }

    // --- epilogue: D fragment scatter + bias ---
    const int g   = lane >> 2;
    const int tig = lane & 3;
#pragma unroll
    for (int mA = 0; mA < 2; mA++) {
        int mbase = wm * 32 + mA * 16;
#pragma unroll
        for (int ntl = 0; ntl < 8; ntl++) {
            int o = wn * 64 + ntl * 8 + 2 * tig;
            float b0v = __ldg(pw_b + o);
            float b1v = __ldg(pw_b + o + 1);
            size_t r0 = (((size_t)(bb * OC_ + o)) * H_ + h) * W_ + w0;
            size_t r1 = r0 + (size_t)H_ * W_;
            const float* a4 = acc[mA][ntl];
            out[r0 + mbase + g]     = a4[0] + b0v;
            out[r1 + mbase + g]     = a4[1] + b1v;
            out[r0 + mbase + g + 8] = a4[2] + b0v;
            out[r1 + mbase + g + 8] = a4[3] + b1v;
        }
    }
}

// ---------------------------------------------------------------------------
extern "C" void kernel_launch(void* const* d_in, const int* in_sizes, int n_in,
                              void* d_out, int out_size) {
    const float* x           = (const float*)d_in[0];
    const float* kernel_bank = (const float*)d_in[1];
    const float* attn_w      = (const float*)d_in[2];
    const float* attn_b      = (const float*)d_in[3];
    const float* pw_w        = (const float*)d_in[4];
    const float* pw_b        = (const float*)d_in[5];
    float* out               = (float*)d_out;

    static int smem_set = 0;
    if (!smem_set) {
        cudaFuncSetAttribute(fused_kernel,
                             cudaFuncAttributeMaxDynamicSharedMemorySize,
                             SMEM_FLOATS * 4);
        smem_set = 1;
    }

    pool_kernel<<<B_ * C_, 256>>>(x);
    attn_kernel<<<B_, 128>>>(kernel_bank, attn_w, attn_b);
    split_pw_frag<<<16, 256>>>(pw_w);
    fused_kernel<<<dim3(W_ / 128, H_, B_), 256, SMEM_FLOATS * 4>>>(x, pw_b, out);
}

// round 8
// speedup vs baseline: 2.8457x; 1.0083x over previous
#include <cuda_runtime.h>
#include <cuda_bf16.h>
#include <cstdint>

// Problem constants
#define B_  8
#define C_  128
#define H_  256
#define W_  256
#define KB_ 4
#define OC_ 128

// Scratch (static device arrays; no allocation)
__device__ float g_pooled[B_ * C_];
__device__ float g_dynk[B_ * C_ * 9];
// pw_w split to bf16 hi + bf16 residual lo, packed in m16n8k16 B-fragment
// order: [ci(8)][nt(16)][lane(32)][4 words: bh0, bh1, bl0, bl1]
__device__ uint32_t g_pwf[8 * 16 * 32 * 4];        // 16384 u32

// ---------------------------------------------------------------------------
// helpers
// ---------------------------------------------------------------------------
__device__ __forceinline__ uint32_t smem_u32(const void* p) {
    uint32_t a;
    asm("{ .reg .u64 t; cvta.to.shared.u64 t, %1; cvt.u32.u64 %0, t; }"
        : "=r"(a) : "l"(p));
    return a;
}
__device__ __forceinline__ void mma_bf16(float* d, const uint32_t* a,
                                         uint32_t b0, uint32_t b1) {
    asm volatile(
        "mma.sync.aligned.m16n8k16.row.col.f32.bf16.bf16.f32 "
        "{%0,%1,%2,%3}, {%4,%5,%6,%7}, {%8,%9}, {%0,%1,%2,%3};"
        : "+f"(d[0]), "+f"(d[1]), "+f"(d[2]), "+f"(d[3])
        : "r"(a[0]), "r"(a[1]), "r"(a[2]), "r"(a[3]), "r"(b0), "r"(b1));
}
// split float into bf16 hi bits + bf16 residual bits
__device__ __forceinline__ uint32_t split_bf16_pair(float v) {
    __nv_bfloat16 h = __float2bfloat16_rn(v);
    float hif = __bfloat162float(h);
    __nv_bfloat16 l = __float2bfloat16_rn(v - hif);
    return (uint32_t)__bfloat16_as_ushort(h)
         | ((uint32_t)__bfloat16_as_ushort(l) << 16);
}

// ---------------------------------------------------------------------------
// Kernel 1: global average pool
// ---------------------------------------------------------------------------
__global__ void pool_kernel(const float* __restrict__ x) {
    const int plane = blockIdx.x;
    const int t = threadIdx.x;
    const float4* p = reinterpret_cast<const float4*>(x + (size_t)plane * (H_ * W_));
    float s = 0.f;
#pragma unroll 8
    for (int it = 0; it < 64; it++) {
        float4 v = p[it * 256 + t];
        s += (v.x + v.y) + (v.z + v.w);
    }
    __shared__ float red[256];
    red[t] = s;
    __syncthreads();
    for (int st = 128; st > 0; st >>= 1) {
        if (t < st) red[t] += red[t + st];
        __syncthreads();
    }
    if (t == 0) g_pooled[plane] = red[0] * (1.f / (H_ * W_));
}

// ---------------------------------------------------------------------------
// Kernel 2: attention -> softmax -> dynamic depthwise kernel per (b,c)
// ---------------------------------------------------------------------------
__global__ void attn_kernel(const float* __restrict__ kernel_bank,
                            const float* __restrict__ attn_w,
                            const float* __restrict__ attn_b) {
    const int b = blockIdx.x;
    const int c = threadIdx.x;               // 128 threads
    __shared__ float red[128];
    __shared__ float logit[KB_];
    __shared__ float attn[KB_];

    float p = g_pooled[b * C_ + c];
    for (int k = 0; k < KB_; k++) {
        red[c] = p * attn_w[k * C_ + c];
        __syncthreads();
        for (int st = 64; st > 0; st >>= 1) {
            if (c < st) red[c] += red[c + st];
            __syncthreads();
        }
        if (c == 0) logit[k] = red[0] + attn_b[k];
        __syncthreads();
    }
    if (c == 0) {
        float mx = logit[0];
        for (int k = 1; k < KB_; k++) mx = fmaxf(mx, logit[k]);
        float s = 0.f;
        for (int k = 0; k < KB_; k++) { attn[k] = expf(logit[k] - mx); s += attn[k]; }
        float inv = 1.f / s;
        for (int k = 0; k < KB_; k++) attn[k] *= inv;
    }
    __syncthreads();
    float a0 = attn[0], a1 = attn[1], a2 = attn[2], a3 = attn[3];
#pragma unroll
    for (int ij = 0; ij < 9; ij++) {
        float s = a0 * kernel_bank[(0 * C_ + c) * 9 + ij]
                + a1 * kernel_bank[(1 * C_ + c) * 9 + ij]
                + a2 * kernel_bank[(2 * C_ + c) * 9 + ij]
                + a3 * kernel_bank[(3 * C_ + c) * 9 + ij];
        g_dynk[(b * C_ + c) * 9 + ij] = s;
    }
}

// ---------------------------------------------------------------------------
// Kernel 2b: split pw_w to bf16 hi/lo, packed in B-fragment order.
// ---------------------------------------------------------------------------
__global__ void split_pw_frag(const float* __restrict__ pw_w) {
    int idx = blockIdx.x * 256 + threadIdx.x;   // (ci, nt, lane)
    if (idx >= 4096) return;
    int lane = idx & 31;
    int nt   = (idx >> 5) & 15;
    int ci   = idx >> 9;
    int g = lane >> 2, tig = lane & 3;
    int o  = nt * 8 + g;
    int k0 = ci * 16 + 2 * tig;

    uint32_t p00 = split_bf16_pair(pw_w[o * C_ + k0]);       // {hi,lo}
    uint32_t p01 = split_bf16_pair(pw_w[o * C_ + k0 + 1]);
    uint32_t p10 = split_bf16_pair(pw_w[o * C_ + k0 + 8]);
    uint32_t p11 = split_bf16_pair(pw_w[o * C_ + k0 + 9]);

    g_pwf[idx * 4 + 0] = __byte_perm(p00, p01, 0x5410);      // bh0
    g_pwf[idx * 4 + 1] = __byte_perm(p10, p11, 0x5410);      // bh1
    g_pwf[idx * 4 + 2] = __byte_perm(p00, p01, 0x7632);      // bl0
    g_pwf[idx * 4 + 3] = __byte_perm(p10, p11, 0x7632);      // bl1
}

// ---------------------------------------------------------------------------
// Fused dw 3x3 + mma.sync bf16 GEMM, M=256 tile (2 output rows per CTA).
// Grid (W/128=2, H/2=128, B=8), 512 threads, 1 CTA/SM.
// dw: warps 0-7 (256 thr): each thread = (kch, mg), 8 px x 2 rows from 4
//     staged xs rows (row reuse: 16 LDS.128 for 16 outputs).
// GEMM: all 16 warps, 4x4 warp grid, warp tile m64 x n32, 48 MMA/chunk.
// Smem (floats):
//   As[2]  : buf stride 4128 (hi 2048 @+0, lo 2048 @+2064)
//   Bs[3]  : each 2048 words {bh0,bh1,bl0,bl1}
//   xs[2]  : 16ch x 4rows x 140, ch stride 564 (pad 4 -> conflict-free)
//   dk     : 1152
// ---------------------------------------------------------------------------
#define XS_ROWST 140
#define XS_CH    564                        // 4*140 + 4 pad (141 mod 8 = 5, odd)
#define XS_FLTS  (16 * XS_CH)               // 9024 per buffer
#define AS_F     0
#define AS_LO_D  2064
#define AS_STRIDE 4128
#define BS_F     8256
#define XS_F     (BS_F + 3 * 2048)          // 14400
#define DK_F     (XS_F + 2 * XS_FLTS)       // 32448
#define SMEM_FLOATS (DK_F + 1152)           // 33600 -> 134400 B

__device__ __forceinline__ void stage_xs(const float* __restrict__ x,
                                         int b, int c0, int h0, int w0,
                                         float* xf, int t) {
    // interior: 16 ch x 4 rows x 32 float4 = 2048 f4, 4 per thread
#pragma unroll
    for (int i = 0; i < 4; i++) {
        int idx = t + i * 512;
        int c   = idx >> 7;
        int rem = idx & 127;
        int r   = rem >> 5;
        int q   = rem & 31;
        int hh  = h0 + r - 1;
        float* dst = xf + c * XS_CH + r * XS_ROWST + 4 + q * 4;
        if ((unsigned)hh < (unsigned)H_) {
            const float* src = x + (((size_t)(b * C_ + c0 + c)) * H_ + hh) * W_ + w0 + q * 4;
            asm volatile("cp.async.cg.shared.global [%0], [%1], 16;"
                         :: "r"(smem_u32(dst)), "l"(src));
        } else {
            *reinterpret_cast<float4*>(dst) = make_float4(0.f, 0.f, 0.f, 0.f);
        }
    }
    // halo columns: 16 ch x 4 rows x 2 sides = 128 scalars
    if (t < 128) {
        int c    = t >> 3;
        int rem  = t & 7;
        int r    = rem >> 1;
        int side = rem & 1;
        int hh   = h0 + r - 1;
        int ww   = side ? (w0 + 128) : (w0 - 1);
        int col  = side ? 132 : 3;
        float* dst = xf + c * XS_CH + r * XS_ROWST + col;
        if ((unsigned)hh < (unsigned)H_ && (unsigned)ww < (unsigned)W_) {
            const float* src = x + (((size_t)(b * C_ + c0 + c)) * H_ + hh) * W_ + ww;
            asm volatile("cp.async.ca.shared.global [%0], [%1], 4;"
                         :: "r"(smem_u32(dst)), "l"(src));
        } else {
            *dst = 0.f;
        }
    }
}

__device__ __forceinline__ void stage_B(int ci, float* bsbuf, int t) {
    // 2048 words = 512 x 16B, one cp.async per thread
    const uint32_t* src = g_pwf + ci * 2048;
    asm volatile("cp.async.cg.shared.global [%0], [%1], 16;"
                 :: "r"(smem_u32(bsbuf) + t * 16u), "l"(src + t * 4));
}

// depthwise for chunk cj (warps 0-7 only)
__device__ __forceinline__ void dw_chunk(float* smem, int cj, int kch, int mg,
                                         int wb0, int wb1, int a_lo_sel,
                                         uint32_t psel) {
    const float* dk   = smem + DK_F;
    const float* dkc  = dk + (cj * 16 + kch) * 9;
    const float* rowb = smem + XS_F + (cj & 1) * XS_FLTS + kch * XS_CH + mg * 8;
    float s0[8], s1[8];
#pragma unroll
    for (int j = 0; j < 8; j++) { s0[j] = 0.f; s1[j] = 0.f; }
#pragma unroll
    for (int r = 0; r < 4; r++) {
        const float* rp = rowb + r * XS_ROWST;
        float4 q0 = *reinterpret_cast<const float4*>(rp);
        float4 q1 = *reinterpret_cast<const float4*>(rp + 4);
        float4 q2 = *reinterpret_cast<const float4*>(rp + 8);
        float4 q3 = *reinterpret_cast<const float4*>(rp + 12);
        float v[16] = {q0.x, q0.y, q0.z, q0.w, q1.x, q1.y, q1.z, q1.w,
                       q2.x, q2.y, q2.z, q2.w, q3.x, q3.y, q3.z, q3.w};
        if (r < 3) {     // contributes to output row 0 with kernel row r
            float k0 = dkc[r * 3 + 0], k1 = dkc[r * 3 + 1], k2 = dkc[r * 3 + 2];
#pragma unroll
            for (int j = 0; j < 8; j++) {
                s0[j] = fmaf(k0, v[j + 3], s0[j]);
                s0[j] = fmaf(k1, v[j + 4], s0[j]);
                s0[j] = fmaf(k2, v[j + 5], s0[j]);
            }
        }
        if (r > 0) {     // contributes to output row 1 with kernel row r-1
            float k0 = dkc[(r - 1) * 3 + 0], k1 = dkc[(r - 1) * 3 + 1],
                  k2 = dkc[(r - 1) * 3 + 2];
#pragma unroll
            for (int j = 0; j < 8; j++) {
                s1[j] = fmaf(k0, v[j + 3], s1[j]);
                s1[j] = fmaf(k1, v[j + 4], s1[j]);
                s1[j] = fmaf(k2, v[j + 5], s1[j]);
            }
        }
    }
    float* abase = smem + AS_F + (cj & 1) * AS_STRIDE + a_lo_sel;
#pragma unroll
    for (int j = 0; j < 8; j++) {
        uint32_t own = split_bf16_pair(s0[j]);
        uint32_t partner = __shfl_xor_sync(0xffffffffu, own, 1);
        abase[wb0 + j * 16] = __uint_as_float(__byte_perm(own, partner, psel));
    }
#pragma unroll
    for (int j = 0; j < 8; j++) {
        uint32_t own = split_bf16_pair(s1[j]);
        uint32_t partner = __shfl_xor_sync(0xffffffffu, own, 1);
        abase[wb1 + j * 16] = __uint_as_float(__byte_perm(own, partner, psel));
    }
}

__global__ __launch_bounds__(512, 1)
void fused_kernel(const float* __restrict__ x,
                  const float* __restrict__ pw_b,
                  float* __restrict__ out) {
    extern __shared__ float smem[];
    float* dk = smem + DK_F;

    const int t    = threadIdx.x;
    const int wid  = t >> 5;
    const int lane = t & 31;
    const int w0   = blockIdx.x * 128;
    const int h0   = blockIdx.y * 2;
    const int bb   = blockIdx.z;

    // dw mapping (threads 0-255): channel kch, 8-pixel group mg
    const int kch = t & 15;
    const int mg  = (t >> 4) & 15;
    const bool is_dw = (t < 256);
    const int wb0 = (mg >> 1) * 128 + ((kch >> 1) & 3) * 4
                  + (kch >> 3) * 2 + (mg & 1);
    const int wb1 = wb0 + 8 * 128;           // row 1: mt += 8
    const int a_lo_sel = (kch & 1) ? AS_LO_D : 0;
    const uint32_t psel = (kch & 1) ? 0x3276u : 0x5410u;

    // GEMM warp tiling: 4 m-warps x 4 n-warps, warp tile m64 x n32
    const int wm = wid & 3;
    const int wn = wid >> 2;

    // prologue
    stage_xs(x, bb, 0, h0, w0, smem + XS_F, t);
    stage_B(0, smem + BS_F, t);
    asm volatile("cp.async.commit_group;" ::: "memory");
    for (int i = t; i < C_ * 9; i += 512)
        dk[i] = g_dynk[bb * C_ * 9 + i];

    float acc[4][4][4];
#pragma unroll
    for (int i = 0; i < 4; i++)
#pragma unroll
        for (int j = 0; j < 4; j++)
#pragma unroll
            for (int k = 0; k < 4; k++) acc[i][j][k] = 0.f;

    asm volatile("cp.async.wait_group 0;" ::: "memory");
    __syncthreads();
    stage_xs(x, bb, 16, h0, w0, smem + XS_F + XS_FLTS, t);
    stage_B(1, smem + BS_F + 2048, t);
    asm volatile("cp.async.commit_group;" ::: "memory");

    if (is_dw) dw_chunk(smem, 0, kch, mg, wb0, wb1, a_lo_sel, psel);

#pragma unroll 1
    for (int ci = 0; ci < 8; ci++) {
        if (ci < 7)
            asm volatile("cp.async.wait_group 0;" ::: "memory");
        __syncthreads();   // dw(ci) visible; GEMM(ci-1) done; xs(ci+1)/B(ci+1) landed

        if (ci < 6) {
            stage_xs(x, bb, (ci + 2) * 16, h0, w0, smem + XS_F + (ci & 1) * XS_FLTS, t);
            stage_B(ci + 2, smem + BS_F + ((ci + 2) % 3) * 2048, t);
            asm volatile("cp.async.commit_group;" ::: "memory");
        }

        // dw(ci+1) on warps 0-7 overlaps GEMM(ci) on all warps
        if (ci < 7 && is_dw)
            dw_chunk(smem, ci + 1, kch, mg, wb0, wb1, a_lo_sel, psel);

        // --- GEMM(ci): one k16 step, 3xBF16 split, 2 m-halves ---
        {
            const float* asb = smem + AS_F + (ci & 1) * AS_STRIDE;
            const float* bsb = smem + BS_F + (ci % 3) * 2048;
#pragma unroll
            for (int half = 0; half < 2; half++) {
                uint4 ah[2], al[2];
#pragma unroll
                for (int mA = 0; mA < 2; mA++) {
                    int mt = wm * 4 + half * 2 + mA;
                    int fi = (mt * 32 + lane) * 4;
                    ah[mA] = *reinterpret_cast<const uint4*>(asb + fi);
                    al[mA] = *reinterpret_cast<const uint4*>(asb + AS_LO_D + fi);
                }
#pragma unroll
                for (int ntl = 0; ntl < 4; ntl++) {
                    int nt = wn * 4 + ntl;
                    uint4 bv = *reinterpret_cast<const uint4*>(bsb + (nt * 32 + lane) * 4);
#pragma unroll
                    for (int mA = 0; mA < 2; mA++) {
                        float* a4 = acc[half * 2 + mA][ntl];
                        mma_bf16(a4, reinterpret_cast<uint32_t*>(&ah[mA]), bv.x, bv.y);
                        mma_bf16(a4, reinterpret_cast<uint32_t*>(&al[mA]), bv.x, bv.y);
                        mma_bf16(a4, reinterpret_cast<uint32_t*>(&ah[mA]), bv.z, bv.w);
                    }
                }
            }
        }
    }

    // --- epilogue: D fragment scatter + bias ---
    const int g   = lane >> 2;
    const int tig = lane & 3;
#pragma unroll
    for (int mA = 0; mA < 4; mA++) {
        int mbase = wm * 64 + mA * 16;
        int h  = h0 + (mbase >> 7);          // mbase..mbase+15 in same row
        int wp = w0 + (mbase & 127);
#pragma unroll
        for (int ntl = 0; ntl < 4; ntl++) {
            int o = wn * 32 + ntl * 8 + 2 * tig;
            float b0v = __ldg(pw_b + o);
            float b1v = __ldg(pw_b + o + 1);
            size_t r0 = (((size_t)(bb * OC_ + o)) * H_ + h) * W_ + wp;
            size_t r1 = r0 + (size_t)H_ * W_;
            const float* a4 = acc[mA][ntl];
            out[r0 + g]     = a4[0] + b0v;
            out[r1 + g]     = a4[1] + b1v;
            out[r0 + g + 8] = a4[2] + b0v;
            out[r1 + g + 8] = a4[3] + b1v;
        }
    }
}

// ---------------------------------------------------------------------------
extern "C" void kernel_launch(void* const* d_in, const int* in_sizes, int n_in,
                              void* d_out, int out_size) {
    const float* x           = (const float*)d_in[0];
    const float* kernel_bank = (const float*)d_in[1];
    const float* attn_w      = (const float*)d_in[2];
    const float* attn_b      = (const float*)d_in[3];
    const float* pw_w        = (const float*)d_in[4];
    const float* pw_b        = (const float*)d_in[5];
    float* out               = (float*)d_out;

    static int smem_set = 0;
    if (!smem_set) {
        cudaFuncSetAttribute(fused_kernel,
                             cudaFuncAttributeMaxDynamicSharedMemorySize,
                             SMEM_FLOATS * 4);
        smem_set = 1;
    }

    pool_kernel<<<B_ * C_, 256>>>(x);
    attn_kernel<<<B_, 128>>>(kernel_bank, attn_w, attn_b);
    split_pw_frag<<<16, 256>>>(pw_w);
    fused_kernel<<<dim3(W_ / 128, H_ / 2, B_), 512, SMEM_FLOATS * 4>>>(x, pw_b, out);
}